// round 3
// baseline (speedup 1.0000x reference)
#include <cuda_runtime.h>
#include <math.h>

#define DIN   8192
#define FDIM  2048
#define BATCH 128
#define NCLS  18
#define NCHUNK 16
#define CHUNK_D (DIN / NCHUNK)   // 512
#define NG_MAX 684
#define USTRIDE 19               // padded to kill LDS bank conflicts

// Scratch (static device globals: allocation-free)
__device__ float g_wbar[3 * DIN];                       // rowsum(Wan) per branch
__device__ float g_M[3 * DIN * NCLS];                   // Wnm @ U per branch
__device__ float g_spart[3 * NCHUNK * BATCH];           // partial x·wbar
__device__ float g_tpart[3 * NCHUNK * BATCH * NCLS];    // partial x·M

// ---------------------------------------------------------------------------
// K1: for each branch, stream Wnm once computing M[d,c] = sum_g wsum[d,g]*Wc[g,c]
//     (group-compressed: 3 consecutive j share a Wc row), and stream Wan once
//     computing row sums. Grid: 3 branches x 64 slabs of 128 rows. 256 thr.
//     Dynamic smem: Wc rows for this branch, padded stride 19 (~52 KB).
// ---------------------------------------------------------------------------
__global__ __launch_bounds__(256, 2)
void k1_prep(const float* __restrict__ Wnm0, const float* __restrict__ Wan0,
             const float* __restrict__ Wnm1, const float* __restrict__ Wan1,
             const float* __restrict__ Wnm2, const float* __restrict__ Wan2,
             const float* __restrict__ Wc)
{
    extern __shared__ float u_sm[];  // [NG][USTRIDE]

    const int br   = blockIdx.x >> 6;
    const int slab = blockIdx.x & 63;
    const float* __restrict__ Wnm = (br == 0) ? Wnm0 : (br == 1) ? Wnm1 : Wnm2;
    const float* __restrict__ Wan = (br == 0) ? Wan0 : (br == 1) ? Wan1 : Wan2;

    const int base_k = br * FDIM;
    const int g_lo   = base_k / 3;
    const int g_hi   = (base_k + FDIM - 1) / 3;
    const int NG     = g_hi - g_lo + 1;   // 683 or 684

    // Stage Wc rows [g_lo, g_hi] into smem, padded stride 19
    for (int idx = threadIdx.x; idx < NG * NCLS; idx += blockDim.x) {
        int g = idx / NCLS;
        int c = idx - g * NCLS;
        u_sm[g * USTRIDE + c] = Wc[(g_lo + g) * NCLS + c];
    }
    __syncthreads();

    const int warp = threadIdx.x >> 5;
    const int lane = threadIdx.x & 31;
    const int row0_blk = slab * 128;

    // ---- group-GEMM: M = Wnm @ U. 4 passes of 4 rows per warp ----
    for (int p = 0; p < 4; p++) {
        const int r0 = row0_blk + warp * 16 + p * 4;
        float acc[4][NCLS];
        #pragma unroll
        for (int r = 0; r < 4; r++)
            #pragma unroll
            for (int c = 0; c < NCLS; c++) acc[r][c] = 0.f;

        const float* __restrict__ wr0 = Wnm + (size_t)(r0 + 0) * FDIM;
        const float* __restrict__ wr1 = Wnm + (size_t)(r0 + 1) * FDIM;
        const float* __restrict__ wr2 = Wnm + (size_t)(r0 + 2) * FDIM;
        const float* __restrict__ wr3 = Wnm + (size_t)(r0 + 3) * FDIM;

        for (int gi = 0; gi < NG; gi += 32) {
            const int gl  = gi + lane;
            const int glc = (gl < NG) ? gl : (NG - 1);
            const int j0  = 3 * (g_lo + gl) - base_k;  // may be <0 or >=FDIM at edges

            float ws0 = 0.f, ws1 = 0.f, ws2 = 0.f, ws3 = 0.f;
            #pragma unroll
            for (int k = 0; k < 3; k++) {
                const int j = j0 + k;
                if (j >= 0 && j < FDIM) {
                    ws0 += wr0[j];
                    ws1 += wr1[j];
                    ws2 += wr2[j];
                    ws3 += wr3[j];
                }
            }
            #pragma unroll
            for (int c = 0; c < NCLS; c++) {
                const float u = u_sm[glc * USTRIDE + c];
                acc[0][c] += ws0 * u;
                acc[1][c] += ws1 * u;
                acc[2][c] += ws2 * u;
                acc[3][c] += ws3 * u;
            }
        }

        #pragma unroll
        for (int r = 0; r < 4; r++) {
            #pragma unroll
            for (int c = 0; c < NCLS; c++) {
                float v = acc[r][c];
                #pragma unroll
                for (int off = 16; off > 0; off >>= 1)
                    v += __shfl_xor_sync(0xffffffffu, v, off);
                acc[r][c] = v;
            }
            if (lane == 0) {
                float* mp = &g_M[(size_t)(br * DIN + r0 + r) * NCLS];
                #pragma unroll
                for (int c = 0; c < NCLS; c++) mp[c] = acc[r][c];
            }
        }
    }

    // ---- Wan row sums: 16 rows per warp, float4 streaming ----
    for (int rr = 0; rr < 16; rr++) {
        const int row = row0_blk + warp * 16 + rr;
        const float4* __restrict__ wa =
            reinterpret_cast<const float4*>(Wan + (size_t)row * FDIM);
        float s = 0.f;
        for (int i = lane; i < FDIM / 4; i += 32) {
            float4 v = wa[i];
            s += (v.x + v.y) + (v.z + v.w);
        }
        #pragma unroll
        for (int off = 16; off > 0; off >>= 1)
            s += __shfl_xor_sync(0xffffffffu, s, off);
        if (lane == 0) g_wbar[br * DIN + row] = s;
    }
}

// ---------------------------------------------------------------------------
// K2: partial dots t_part[b,c] += x[b,d]*M[d,c], s_part[b] += x[b,d]*wbar[d]
//     Grid: 3 branches x 16 d-chunks (512 each). One warp per batch row.
// ---------------------------------------------------------------------------
__global__ __launch_bounds__(256)
void k2_xdot(const float* __restrict__ xd,
             const float* __restrict__ xr,
             const float* __restrict__ xt)
{
    __shared__ float Msm[CHUNK_D * USTRIDE];
    __shared__ float wbsm[CHUNK_D];

    const int br    = blockIdx.x >> 4;
    const int chunk = blockIdx.x & 15;
    const int d0    = chunk * CHUNK_D;
    const float* __restrict__ x = (br == 0) ? xd : (br == 1) ? xr : xt;

    for (int idx = threadIdx.x; idx < CHUNK_D * NCLS; idx += blockDim.x) {
        int d = idx / NCLS;
        int c = idx - d * NCLS;
        Msm[d * USTRIDE + c] = g_M[(size_t)(br * DIN + d0 + d) * NCLS + c];
    }
    for (int d = threadIdx.x; d < CHUNK_D; d += blockDim.x)
        wbsm[d] = g_wbar[br * DIN + d0 + d];
    __syncthreads();

    const int warp = threadIdx.x >> 5;
    const int lane = threadIdx.x & 31;

    for (int b = warp; b < BATCH; b += 8) {
        const float* __restrict__ xb = x + (size_t)b * DIN + d0;
        float acc[NCLS + 1];
        #pragma unroll
        for (int c = 0; c <= NCLS; c++) acc[c] = 0.f;

        #pragma unroll 4
        for (int i = 0; i < CHUNK_D / 32; i++) {
            const int d = i * 32 + lane;
            const float xv = xb[d];
            #pragma unroll
            for (int c = 0; c < NCLS; c++)
                acc[c] += xv * Msm[d * USTRIDE + c];
            acc[NCLS] += xv * wbsm[d];
        }

        #pragma unroll
        for (int c = 0; c <= NCLS; c++) {
            float v = acc[c];
            #pragma unroll
            for (int off = 16; off > 0; off >>= 1)
                v += __shfl_xor_sync(0xffffffffu, v, off);
            acc[c] = v;
        }
        if (lane == 0) {
            float* tp = &g_tpart[(size_t)((br * NCHUNK + chunk) * BATCH + b) * NCLS];
            #pragma unroll
            for (int c = 0; c < NCLS; c++) tp[c] = acc[c];
            g_spart[(br * NCHUNK + chunk) * BATCH + b] = acc[NCLS];
        }
    }
}

// ---------------------------------------------------------------------------
// K3: reduce partials, logits = (1/(3F)) * sum_br s_br * t_br + bc, softmax.
//     Grid: 128 blocks (one per batch row), 32 threads (lane = class).
// ---------------------------------------------------------------------------
__global__ __launch_bounds__(32)
void k3_final(const float* __restrict__ bc, float* __restrict__ out)
{
    const int b    = blockIdx.x;
    const int lane = threadIdx.x;

    float logit = -3.402823466e38f;
    if (lane < NCLS) {
        float acc = 0.f;
        #pragma unroll
        for (int br = 0; br < 3; br++) {
            float sv = 0.f, tv = 0.f;
            #pragma unroll
            for (int k = 0; k < NCHUNK; k++) {
                sv += g_spart[(br * NCHUNK + k) * BATCH + b];
                tv += g_tpart[(size_t)((br * NCHUNK + k) * BATCH + b) * NCLS + lane];
            }
            acc += sv * tv;
        }
        logit = acc * (1.f / (3.f * (float)FDIM)) + bc[lane];
    }

    float m = logit;
    #pragma unroll
    for (int off = 16; off > 0; off >>= 1)
        m = fmaxf(m, __shfl_xor_sync(0xffffffffu, m, off));
    const float e = (lane < NCLS) ? expf(logit - m) : 0.f;
    float sum = e;
    #pragma unroll
    for (int off = 16; off > 0; off >>= 1)
        sum += __shfl_xor_sync(0xffffffffu, sum, off);
    if (lane < NCLS) out[b * NCLS + lane] = e / sum;
}

// ---------------------------------------------------------------------------
extern "C" void kernel_launch(void* const* d_in, const int* in_sizes, int n_in,
                              void* d_out, int out_size)
{
    const float* xd    = (const float*)d_in[0];
    const float* xr    = (const float*)d_in[1];
    const float* xt    = (const float*)d_in[2];
    const float* Wd_nm = (const float*)d_in[3];
    const float* Wd_an = (const float*)d_in[4];
    const float* Wr_nm = (const float*)d_in[5];
    const float* Wr_an = (const float*)d_in[6];
    const float* Wt_nm = (const float*)d_in[7];
    const float* Wt_an = (const float*)d_in[8];
    const float* Wc    = (const float*)d_in[9];
    const float* bc    = (const float*)d_in[10];

    const int smem1 = NG_MAX * USTRIDE * (int)sizeof(float);  // 51984 B
    cudaFuncSetAttribute(k1_prep, cudaFuncAttributeMaxDynamicSharedMemorySize, smem1);

    k1_prep<<<3 * 64, 256, smem1>>>(Wd_nm, Wd_an, Wr_nm, Wr_an, Wt_nm, Wt_an, Wc);
    k2_xdot<<<3 * NCHUNK, 256>>>(xd, xr, xt);
    k3_final<<<BATCH, 32>>>(bc, (float*)d_out);
}

// round 5
// speedup vs baseline: 1.2877x; 1.2877x over previous
#include <cuda_runtime.h>
#include <math.h>

#define DIN   8192
#define FDIM  2048
#define BATCH 128
#define NCLS  18
#define NCHUNK 16
#define CHUNK_D (DIN / NCHUNK)   // 512
#define NG_MAX 684
#define USTRIDE 19               // padded: stride-19 LDS is conflict-free
#define K2_BGRP 4                // batch groups in K2

// Scratch (static device globals: allocation-free)
__device__ float g_wbar[3 * DIN];                       // rowsum(Wan) per branch
__device__ float g_M[3 * DIN * NCLS];                   // Wnm @ U per branch
__device__ float g_spart[3 * NCHUNK * BATCH];           // partial x.wbar
__device__ float g_tpart[3 * NCHUNK * BATCH * NCLS];    // partial x.M

// ---------------------------------------------------------------------------
// K1: per branch, stream Wnm once: M[d,c] = sum_g (sum of 3 consecutive
//     Wnm[d,j] in group g) * Wc[g,c]; stream Wan once: row sums.
//     Grid: 3 branches x 128 slabs of 64 rows. 256 thr, 2-row reg blocking,
//     4 blocks/SM (50% occ). Edge predication only in first/last g-window.
// ---------------------------------------------------------------------------
__global__ __launch_bounds__(256, 4)
void k1_prep(const float* __restrict__ Wnm0, const float* __restrict__ Wan0,
             const float* __restrict__ Wnm1, const float* __restrict__ Wan1,
             const float* __restrict__ Wnm2, const float* __restrict__ Wan2,
             const float* __restrict__ Wc)
{
    extern __shared__ float u_sm[];  // [NG][USTRIDE]

    const int br   = blockIdx.x >> 7;
    const int slab = blockIdx.x & 127;
    const float* __restrict__ Wnm = (br == 0) ? Wnm0 : (br == 1) ? Wnm1 : Wnm2;
    const float* __restrict__ Wan = (br == 0) ? Wan0 : (br == 1) ? Wan1 : Wan2;

    const int base_k = br * FDIM;
    const int g_lo   = base_k / 3;
    const int g_hi   = (base_k + FDIM - 1) / 3;
    const int NG     = g_hi - g_lo + 1;   // 683 or 684

    // Stage Wc rows [g_lo, g_hi] into smem, padded stride 19
    for (int idx = threadIdx.x; idx < NG * NCLS; idx += blockDim.x) {
        int g = idx / NCLS;
        int c = idx - g * NCLS;
        u_sm[g * USTRIDE + c] = Wc[(g_lo + g) * NCLS + c];
    }
    __syncthreads();

    const int warp = threadIdx.x >> 5;
    const int lane = threadIdx.x & 31;
    const int row0_blk = slab * 64;
    const int nwin = (NG + 31) >> 5;

    // ---- group-GEMM: 4 passes of 2 rows per warp (8 rows/warp total) ----
    for (int p = 0; p < 4; p++) {
        const int r0 = row0_blk + warp * 8 + p * 2;
        float acc0[NCLS], acc1[NCLS];
        #pragma unroll
        for (int c = 0; c < NCLS; c++) { acc0[c] = 0.f; acc1[c] = 0.f; }

        const float* __restrict__ wr0 = Wnm + (size_t)r0 * FDIM;
        const float* __restrict__ wr1 = wr0 + FDIM;

        for (int w = 0; w < nwin; w++) {
            const int gl  = (w << 5) + lane;
            const int glc = (gl < NG) ? gl : (NG - 1);
            const int j0  = 3 * (g_lo + glc) - base_k;

            float ws0, ws1;
            if (w != 0 && w != nwin - 1) {
                // interior window: 0 <= j0 and j0+2 < FDIM guaranteed
                ws0 = __ldcs(wr0 + j0) + __ldcs(wr0 + j0 + 1) + __ldcs(wr0 + j0 + 2);
                ws1 = __ldcs(wr1 + j0) + __ldcs(wr1 + j0 + 1) + __ldcs(wr1 + j0 + 2);
            } else {
                ws0 = 0.f; ws1 = 0.f;
                #pragma unroll
                for (int k = 0; k < 3; k++) {
                    const int j = j0 + k;
                    if (gl < NG && j >= 0 && j < FDIM) {
                        ws0 += __ldcs(wr0 + j);
                        ws1 += __ldcs(wr1 + j);
                    }
                }
            }
            const float* __restrict__ up = &u_sm[glc * USTRIDE];
            #pragma unroll
            for (int c = 0; c < NCLS; c++) {
                const float u = up[c];
                acc0[c] += ws0 * u;
                acc1[c] += ws1 * u;
            }
        }

        #pragma unroll
        for (int c = 0; c < NCLS; c++) {
            float v0 = acc0[c], v1 = acc1[c];
            #pragma unroll
            for (int off = 16; off > 0; off >>= 1) {
                v0 += __shfl_xor_sync(0xffffffffu, v0, off);
                v1 += __shfl_xor_sync(0xffffffffu, v1, off);
            }
            acc0[c] = v0; acc1[c] = v1;
        }
        if (lane == 0) {
            float* m0 = &g_M[(size_t)(br * DIN + r0) * NCLS];
            float* m1 = m0 + NCLS;
            #pragma unroll
            for (int c = 0; c < NCLS; c++) { m0[c] = acc0[c]; m1[c] = acc1[c]; }
        }
    }

    // ---- Wan row sums: 8 rows per warp, float4 streaming ----
    for (int rr = 0; rr < 8; rr++) {
        const int row = row0_blk + warp * 8 + rr;
        const float4* __restrict__ wa =
            reinterpret_cast<const float4*>(Wan + (size_t)row * FDIM);
        float s = 0.f;
        #pragma unroll 4
        for (int i = lane; i < FDIM / 4; i += 32) {
            float4 v = __ldcs(wa + i);
            s += (v.x + v.y) + (v.z + v.w);
        }
        #pragma unroll
        for (int off = 16; off > 0; off >>= 1)
            s += __shfl_xor_sync(0xffffffffu, s, off);
        if (lane == 0) g_wbar[br * DIN + row] = s;
    }
}

// ---------------------------------------------------------------------------
// K2: t_part[b,c] += x[b,d]*M[d,c], s_part[b] += x[b,d]*wbar[d].
//     Grid: 3 x 16 chunks x 4 batch-groups = 192 blocks, 128 thr.
//     4-row register blocking amortizes M smem reads; M stored in mod-4
//     split layout so float4 (lane-stride-4) access is conflict-free.
// ---------------------------------------------------------------------------
__global__ __launch_bounds__(128)
void k2_xdot(const float* __restrict__ xd,
             const float* __restrict__ xr,
             const float* __restrict__ xt)
{
    __shared__ float Msm[4][(CHUNK_D / 4) * USTRIDE];  // 4 x 128 x 19
    __shared__ float wbsm[CHUNK_D];

    const int bidx  = blockIdx.x;
    const int br    = bidx / (NCHUNK * K2_BGRP);
    const int rem   = bidx - br * (NCHUNK * K2_BGRP);
    const int chunk = rem / K2_BGRP;
    const int bg    = rem - chunk * K2_BGRP;
    const int d0    = chunk * CHUNK_D;
    const float* __restrict__ x = (br == 0) ? xd : (br == 1) ? xr : xt;

    for (int idx = threadIdx.x; idx < CHUNK_D * NCLS; idx += blockDim.x) {
        int dd = idx / NCLS;
        int c  = idx - dd * NCLS;
        Msm[dd & 3][(dd >> 2) * USTRIDE + c] =
            g_M[(size_t)(br * DIN + d0 + dd) * NCLS + c];
    }
    for (int d = threadIdx.x; d < CHUNK_D; d += blockDim.x)
        wbsm[d] = g_wbar[br * DIN + d0 + d];
    __syncthreads();

    const int warp = threadIdx.x >> 5;
    const int lane = threadIdx.x & 31;

    for (int pass = 0; pass < 2; pass++) {
        const int b0 = bg * 32 + warp * 8 + pass * 4;  // 4 batch rows per warp
        float acc[4][NCLS];
        float sacc[4];
        #pragma unroll
        for (int r = 0; r < 4; r++) {
            sacc[r] = 0.f;
            #pragma unroll
            for (int c = 0; c < NCLS; c++) acc[r][c] = 0.f;
        }

        #pragma unroll
        for (int i = 0; i < CHUNK_D / 128; i++) {
            const int dd = i * 128 + 4 * lane;
            float4 xv[4];
            #pragma unroll
            for (int r = 0; r < 4; r++)
                xv[r] = *reinterpret_cast<const float4*>(
                    x + (size_t)(b0 + r) * DIN + d0 + dd);
            const float4 wb = *reinterpret_cast<const float4*>(&wbsm[dd]);
            const float* wbp = reinterpret_cast<const float*>(&wb);
            const int mrow = (i * 32 + lane) * USTRIDE;

            #pragma unroll
            for (int q = 0; q < 4; q++) {
                const float* __restrict__ mq = &Msm[q][mrow];
                float xq[4];
                #pragma unroll
                for (int r = 0; r < 4; r++)
                    xq[r] = reinterpret_cast<const float*>(&xv[r])[q];
                #pragma unroll
                for (int c = 0; c < NCLS; c++) {
                    const float m = mq[c];
                    acc[0][c] += xq[0] * m;
                    acc[1][c] += xq[1] * m;
                    acc[2][c] += xq[2] * m;
                    acc[3][c] += xq[3] * m;
                }
                const float w = wbp[q];
                #pragma unroll
                for (int r = 0; r < 4; r++) sacc[r] += xq[r] * w;
            }
        }

        #pragma unroll
        for (int r = 0; r < 4; r++) {
            #pragma unroll
            for (int c = 0; c < NCLS; c++) {
                float v = acc[r][c];
                #pragma unroll
                for (int off = 16; off > 0; off >>= 1)
                    v += __shfl_xor_sync(0xffffffffu, v, off);
                acc[r][c] = v;
            }
            float sv = sacc[r];
            #pragma unroll
            for (int off = 16; off > 0; off >>= 1)
                sv += __shfl_xor_sync(0xffffffffu, sv, off);
            sacc[r] = sv;
        }
        if (lane == 0) {
            #pragma unroll
            for (int r = 0; r < 4; r++) {
                const int b = b0 + r;
                float* tp = &g_tpart[(size_t)((br * NCHUNK + chunk) * BATCH + b) * NCLS];
                #pragma unroll
                for (int c = 0; c < NCLS; c++) tp[c] = acc[r][c];
                g_spart[(br * NCHUNK + chunk) * BATCH + b] = sacc[r];
            }
        }
    }
}

// ---------------------------------------------------------------------------
// K3: reduce partials, logits = (1/(3F)) * sum_br s_br * t_br + bc, softmax.
// ---------------------------------------------------------------------------
__global__ __launch_bounds__(32)
void k3_final(const float* __restrict__ bc, float* __restrict__ out)
{
    const int b    = blockIdx.x;
    const int lane = threadIdx.x;

    float logit = -3.402823466e38f;
    if (lane < NCLS) {
        float acc = 0.f;
        #pragma unroll
        for (int br = 0; br < 3; br++) {
            float sv = 0.f, tv = 0.f;
            #pragma unroll
            for (int k = 0; k < NCHUNK; k++) {
                sv += g_spart[(br * NCHUNK + k) * BATCH + b];
                tv += g_tpart[(size_t)((br * NCHUNK + k) * BATCH + b) * NCLS + lane];
            }
            acc += sv * tv;
        }
        logit = acc * (1.f / (3.f * (float)FDIM)) + bc[lane];
    }

    float m = logit;
    #pragma unroll
    for (int off = 16; off > 0; off >>= 1)
        m = fmaxf(m, __shfl_xor_sync(0xffffffffu, m, off));
    const float e = (lane < NCLS) ? expf(logit - m) : 0.f;
    float sum = e;
    #pragma unroll
    for (int off = 16; off > 0; off >>= 1)
        sum += __shfl_xor_sync(0xffffffffu, sum, off);
    if (lane < NCLS) out[b * NCLS + lane] = e / sum;
}

// ---------------------------------------------------------------------------
extern "C" void kernel_launch(void* const* d_in, const int* in_sizes, int n_in,
                              void* d_out, int out_size)
{
    const float* xd    = (const float*)d_in[0];
    const float* xr    = (const float*)d_in[1];
    const float* xt    = (const float*)d_in[2];
    const float* Wd_nm = (const float*)d_in[3];
    const float* Wd_an = (const float*)d_in[4];
    const float* Wr_nm = (const float*)d_in[5];
    const float* Wr_an = (const float*)d_in[6];
    const float* Wt_nm = (const float*)d_in[7];
    const float* Wt_an = (const float*)d_in[8];
    const float* Wc    = (const float*)d_in[9];
    const float* bc    = (const float*)d_in[10];

    const int smem1 = NG_MAX * USTRIDE * (int)sizeof(float);  // 51984 B
    cudaFuncSetAttribute(k1_prep, cudaFuncAttributeMaxDynamicSharedMemorySize, smem1);

    k1_prep<<<3 * 128, 256, smem1>>>(Wd_nm, Wd_an, Wr_nm, Wr_an, Wt_nm, Wt_an, Wc);
    k2_xdot<<<3 * NCHUNK * K2_BGRP, 128>>>(xd, xr, xt);
    k3_final<<<BATCH, 32>>>(bc, (float*)d_out);
}

// round 8
// speedup vs baseline: 1.5853x; 1.2311x over previous
#include <cuda_runtime.h>
#include <math.h>

#define DIN   8192
#define FDIM  2048
#define BATCH 128
#define NCLS  18
#define NCHUNK 16
#define CHUNK_D (DIN / NCHUNK)   // 512
#define NG_MAX 684
#define NWIN   22                // ceil(NG/32) == 22 for all three branches
#define USTRIDE 19               // padded: stride-19 LDS is conflict-free
#define K2_BGRP 4                // batch groups in K2

// Scratch (static device globals: allocation-free)
__device__ float g_wbar[3 * DIN];                       // rowsum(Wan) per branch
__device__ float g_M[3 * DIN * NCLS];                   // Wnm @ U per branch
__device__ float g_spart[3 * NCHUNK * BATCH];           // partial x.wbar
__device__ float g_tpart[3 * NCHUNK * BATCH * NCLS];    // partial x.M

// ---------------------------------------------------------------------------
// K1: per branch, stream Wnm once: M[d,c] = sum_g (sum of 3 consecutive
//     Wnm[d,j] in group g) * Wc[g,c]; stream Wan once: row sums.
//     Grid: 3 branches x 128 slabs of 64 rows; 256 thr; 2-row reg blocking;
//     3 blocks/SM (reg headroom for load batching). Edge windows (w=0,21)
//     peeled; interior loop (w=1..20) branch-free and fully unrolled so
//     ptxas front-batches LDGs (deep MLP) and pipelines past the FMA blocks.
// ---------------------------------------------------------------------------
__global__ __launch_bounds__(256, 3)
void k1_prep(const float* __restrict__ Wnm0, const float* __restrict__ Wan0,
             const float* __restrict__ Wnm1, const float* __restrict__ Wan1,
             const float* __restrict__ Wnm2, const float* __restrict__ Wan2,
             const float* __restrict__ Wc)
{
    extern __shared__ float u_sm[];  // [NG][USTRIDE]

    const int br   = blockIdx.x >> 7;
    const int slab = blockIdx.x & 127;
    const float* __restrict__ Wnm = (br == 0) ? Wnm0 : (br == 1) ? Wnm1 : Wnm2;
    const float* __restrict__ Wan = (br == 0) ? Wan0 : (br == 1) ? Wan1 : Wan2;

    const int base_k = br * FDIM;
    const int g_lo   = base_k / 3;
    const int g_hi   = (base_k + FDIM - 1) / 3;
    const int NG     = g_hi - g_lo + 1;   // 683 or 684  (ceil/32 == NWIN)

    // Stage Wc rows [g_lo, g_hi] into smem, padded stride 19
    for (int idx = threadIdx.x; idx < NG * NCLS; idx += blockDim.x) {
        int g = idx / NCLS;
        int c = idx - g * NCLS;
        u_sm[g * USTRIDE + c] = Wc[(g_lo + g) * NCLS + c];
    }
    __syncthreads();

    const int warp = threadIdx.x >> 5;
    const int lane = threadIdx.x & 31;
    const int row0_blk = slab * 64;

    // ---- group-GEMM: 4 passes of 2 rows per warp (8 rows/warp total) ----
    for (int p = 0; p < 4; p++) {
        const int r0 = row0_blk + warp * 8 + p * 2;
        float acc0[NCLS], acc1[NCLS];
        #pragma unroll
        for (int c = 0; c < NCLS; c++) { acc0[c] = 0.f; acc1[c] = 0.f; }

        const float* __restrict__ wr0 = Wnm + (size_t)r0 * FDIM;
        const float* __restrict__ wr1 = wr0 + FDIM;

        // -- edge windows w=0 and w=NWIN-1: fully predicated --
        #pragma unroll
        for (int we = 0; we < 2; we++) {
            const int w   = (we == 0) ? 0 : (NWIN - 1);
            const int gl  = (w << 5) + lane;
            const int glc = (gl < NG) ? gl : (NG - 1);
            const int j0  = 3 * (g_lo + glc) - base_k;

            float ws0 = 0.f, ws1 = 0.f;
            #pragma unroll
            for (int k = 0; k < 3; k++) {
                const int j = j0 + k;
                if (gl < NG && j >= 0 && j < FDIM) {
                    ws0 += __ldcs(wr0 + j);
                    ws1 += __ldcs(wr1 + j);
                }
            }
            const float* __restrict__ up = &u_sm[glc * USTRIDE];
            #pragma unroll
            for (int c = 0; c < NCLS; c++) {
                const float u = up[c];
                acc0[c] += ws0 * u;
                acc1[c] += ws1 * u;
            }
        }

        // -- interior windows w=1..NWIN-2: branch-free, compile-time trip --
        // (proved: for all branches/lanes here, gl < NG, 0 <= j0, j0+2 < FDIM)
        #pragma unroll
        for (int w = 1; w < NWIN - 1; w++) {
            const int gl = (w << 5) + lane;
            const int j0 = 3 * (g_lo + gl) - base_k;

            const float a0 = __ldcs(wr0 + j0);
            const float a1 = __ldcs(wr0 + j0 + 1);
            const float a2 = __ldcs(wr0 + j0 + 2);
            const float b0 = __ldcs(wr1 + j0);
            const float b1 = __ldcs(wr1 + j0 + 1);
            const float b2 = __ldcs(wr1 + j0 + 2);

            const float ws0 = a0 + a1 + a2;
            const float ws1 = b0 + b1 + b2;

            const float* __restrict__ up = &u_sm[gl * USTRIDE];
            #pragma unroll
            for (int c = 0; c < NCLS; c++) {
                const float u = up[c];
                acc0[c] += ws0 * u;
                acc1[c] += ws1 * u;
            }
        }

        #pragma unroll
        for (int c = 0; c < NCLS; c++) {
            float v0 = acc0[c], v1 = acc1[c];
            #pragma unroll
            for (int off = 16; off > 0; off >>= 1) {
                v0 += __shfl_xor_sync(0xffffffffu, v0, off);
                v1 += __shfl_xor_sync(0xffffffffu, v1, off);
            }
            acc0[c] = v0; acc1[c] = v1;
        }
        if (lane == 0) {
            float* m0 = &g_M[(size_t)(br * DIN + r0) * NCLS];
            float* m1 = m0 + NCLS;
            #pragma unroll
            for (int c = 0; c < NCLS; c++) { m0[c] = acc0[c]; m1[c] = acc1[c]; }
        }
    }

    // ---- Wan row sums: 8 rows per warp, float4 streaming ----
    for (int rr = 0; rr < 8; rr++) {
        const int row = row0_blk + warp * 8 + rr;
        const float4* __restrict__ wa =
            reinterpret_cast<const float4*>(Wan + (size_t)row * FDIM);
        float s = 0.f;
        #pragma unroll 4
        for (int i = lane; i < FDIM / 4; i += 32) {
            float4 v = __ldcs(wa + i);
            s += (v.x + v.y) + (v.z + v.w);
        }
        #pragma unroll
        for (int off = 16; off > 0; off >>= 1)
            s += __shfl_xor_sync(0xffffffffu, s, off);
        if (lane == 0) g_wbar[br * DIN + row] = s;
    }
}

// ---------------------------------------------------------------------------
// K2: t_part[b,c] += x[b,d]*M[d,c], s_part[b] += x[b,d]*wbar[d].
//     Grid: 3 x 16 chunks x 4 batch-groups = 192 blocks, 128 thr.
//     4-row register blocking amortizes M smem reads; M stored in mod-4
//     split layout so float4 (lane-stride-4) access is conflict-free.
// ---------------------------------------------------------------------------
__global__ __launch_bounds__(128)
void k2_xdot(const float* __restrict__ xd,
             const float* __restrict__ xr,
             const float* __restrict__ xt)
{
    __shared__ float Msm[4][(CHUNK_D / 4) * USTRIDE];  // 4 x 128 x 19
    __shared__ float wbsm[CHUNK_D];

    const int bidx  = blockIdx.x;
    const int br    = bidx / (NCHUNK * K2_BGRP);
    const int rem   = bidx - br * (NCHUNK * K2_BGRP);
    const int chunk = rem / K2_BGRP;
    const int bg    = rem - chunk * K2_BGRP;
    const int d0    = chunk * CHUNK_D;
    const float* __restrict__ x = (br == 0) ? xd : (br == 1) ? xr : xt;

    for (int idx = threadIdx.x; idx < CHUNK_D * NCLS; idx += blockDim.x) {
        int dd = idx / NCLS;
        int c  = idx - dd * NCLS;
        Msm[dd & 3][(dd >> 2) * USTRIDE + c] =
            g_M[(size_t)(br * DIN + d0 + dd) * NCLS + c];
    }
    for (int d = threadIdx.x; d < CHUNK_D; d += blockDim.x)
        wbsm[d] = g_wbar[br * DIN + d0 + d];
    __syncthreads();

    const int warp = threadIdx.x >> 5;
    const int lane = threadIdx.x & 31;

    for (int pass = 0; pass < 2; pass++) {
        const int b0 = bg * 32 + warp * 8 + pass * 4;  // 4 batch rows per warp
        float acc[4][NCLS];
        float sacc[4];
        #pragma unroll
        for (int r = 0; r < 4; r++) {
            sacc[r] = 0.f;
            #pragma unroll
            for (int c = 0; c < NCLS; c++) acc[r][c] = 0.f;
        }

        #pragma unroll
        for (int i = 0; i < CHUNK_D / 128; i++) {
            const int dd = i * 128 + 4 * lane;
            float4 xv[4];
            #pragma unroll
            for (int r = 0; r < 4; r++)
                xv[r] = *reinterpret_cast<const float4*>(
                    x + (size_t)(b0 + r) * DIN + d0 + dd);
            const float4 wb = *reinterpret_cast<const float4*>(&wbsm[dd]);
            const float* wbp = reinterpret_cast<const float*>(&wb);
            const int mrow = (i * 32 + lane) * USTRIDE;

            #pragma unroll
            for (int q = 0; q < 4; q++) {
                const float* __restrict__ mq = &Msm[q][mrow];
                float xq[4];
                #pragma unroll
                for (int r = 0; r < 4; r++)
                    xq[r] = reinterpret_cast<const float*>(&xv[r])[q];
                #pragma unroll
                for (int c = 0; c < NCLS; c++) {
                    const float m = mq[c];
                    acc[0][c] += xq[0] * m;
                    acc[1][c] += xq[1] * m;
                    acc[2][c] += xq[2] * m;
                    acc[3][c] += xq[3] * m;
                }
                const float w = wbp[q];
                #pragma unroll
                for (int r = 0; r < 4; r++) sacc[r] += xq[r] * w;
            }
        }

        #pragma unroll
        for (int r = 0; r < 4; r++) {
            #pragma unroll
            for (int c = 0; c < NCLS; c++) {
                float v = acc[r][c];
                #pragma unroll
                for (int off = 16; off > 0; off >>= 1)
                    v += __shfl_xor_sync(0xffffffffu, v, off);
                acc[r][c] = v;
            }
            float sv = sacc[r];
            #pragma unroll
            for (int off = 16; off > 0; off >>= 1)
                sv += __shfl_xor_sync(0xffffffffu, sv, off);
            sacc[r] = sv;
        }
        if (lane == 0) {
            #pragma unroll
            for (int r = 0; r < 4; r++) {
                const int b = b0 + r;
                float* tp = &g_tpart[(size_t)((br * NCHUNK + chunk) * BATCH + b) * NCLS];
                #pragma unroll
                for (int c = 0; c < NCLS; c++) tp[c] = acc[r][c];
                g_spart[(br * NCHUNK + chunk) * BATCH + b] = sacc[r];
            }
        }
    }
}

// ---------------------------------------------------------------------------
// K3: reduce partials, logits = (1/(3F)) * sum_br s_br * t_br + bc, softmax.
// ---------------------------------------------------------------------------
__global__ __launch_bounds__(32)
void k3_final(const float* __restrict__ bc, float* __restrict__ out)
{
    const int b    = blockIdx.x;
    const int lane = threadIdx.x;

    float logit = -3.402823466e38f;
    if (lane < NCLS) {
        float acc = 0.f;
        #pragma unroll
        for (int br = 0; br < 3; br++) {
            float sv = 0.f, tv = 0.f;
            #pragma unroll
            for (int k = 0; k < NCHUNK; k++) {
                sv += g_spart[(br * NCHUNK + k) * BATCH + b];
                tv += g_tpart[(size_t)((br * NCHUNK + k) * BATCH + b) * NCLS + lane];
            }
            acc += sv * tv;
        }
        logit = acc * (1.f / (3.f * (float)FDIM)) + bc[lane];
    }

    float m = logit;
    #pragma unroll
    for (int off = 16; off > 0; off >>= 1)
        m = fmaxf(m, __shfl_xor_sync(0xffffffffu, m, off));
    const float e = (lane < NCLS) ? expf(logit - m) : 0.f;
    float sum = e;
    #pragma unroll
    for (int off = 16; off > 0; off >>= 1)
        sum += __shfl_xor_sync(0xffffffffu, sum, off);
    if (lane < NCLS) out[b * NCLS + lane] = e / sum;
}

// ---------------------------------------------------------------------------
extern "C" void kernel_launch(void* const* d_in, const int* in_sizes, int n_in,
                              void* d_out, int out_size)
{
    const float* xd    = (const float*)d_in[0];
    const float* xr    = (const float*)d_in[1];
    const float* xt    = (const float*)d_in[2];
    const float* Wd_nm = (const float*)d_in[3];
    const float* Wd_an = (const float*)d_in[4];
    const float* Wr_nm = (const float*)d_in[5];
    const float* Wr_an = (const float*)d_in[6];
    const float* Wt_nm = (const float*)d_in[7];
    const float* Wt_an = (const float*)d_in[8];
    const float* Wc    = (const float*)d_in[9];
    const float* bc    = (const float*)d_in[10];

    const int smem1 = NG_MAX * USTRIDE * (int)sizeof(float);  // 51984 B
    cudaFuncSetAttribute(k1_prep, cudaFuncAttributeMaxDynamicSharedMemorySize, smem1);

    k1_prep<<<3 * 128, 256, smem1>>>(Wd_nm, Wd_an, Wr_nm, Wr_an, Wt_nm, Wt_an, Wc);
    k2_xdot<<<3 * NCHUNK * K2_BGRP, 128>>>(xd, xr, xt);
    k3_final<<<BATCH, 32>>>(bc, (float*)d_out);
}